// round 14
// baseline (speedup 1.0000x reference)
#include <cuda_runtime.h>
#include <cuda_fp16.h>
#include <cstdint>

// GeneralConv: out[i] += W[k] @ x[j], E=2M, G=4 groups 16->16, + bias.
// R9: x pre-converted to fp16 (1-line rows -> 2 wavefronts/edge), fp32 math via
// cvt+FFMA2; warp-aggregated counting sort; batched shfl-distributed indices.
// Exactly 4 launches: prep, scan, scatter, compute.

static constexpr int CAP  = 2200000;
static constexpr int SEG  = 16384;
static constexpr int MAXB = (CAP + SEG - 1) / SEG + 1;
static constexpr int NMAX = 100352;                       // max nodes
static constexpr unsigned FULL = 0xFFFFFFFFu;

__device__ int2 g_pij[CAP];
__device__ int  g_bc[MAXB * 27];
__device__ int  g_bbase[MAXB * 27];
__device__ int  g_offsets[28];
__device__ __align__(128) __half g_xh[NMAX * 64];         // fp16 copy of x

// Launch 0: per-block k-hist (warp-aggregated) + bias init + x->fp16 convert.
__global__ void prep_kernel(const int* __restrict__ ek, int E,
                            float* __restrict__ out,
                            const float* __restrict__ bias, int total,
                            const float* __restrict__ x, int nx, int nhb) {
    const int lane = threadIdx.x & 31;
    if (blockIdx.x < nhb) {
        __shared__ int c[27];
        if (threadIdx.x < 27) c[threadIdx.x] = 0;
        __syncthreads();
        const int b0 = blockIdx.x * SEG;
        const int b1 = min(E, b0 + SEG);
        for (int base = b0 + (threadIdx.x - lane); base < b1; base += blockDim.x) {
            const int e = base + lane;
            unsigned act = __ballot_sync(FULL, e < b1);
            if (e < b1) {
                int kk = ek[e];
                unsigned m = __match_any_sync(act, kk);
                if (lane == __ffs(m) - 1) atomicAdd(&c[kk], __popc(m));
            }
        }
        __syncthreads();
        if (threadIdx.x < 27) g_bc[blockIdx.x * 27 + threadIdx.x] = c[threadIdx.x];
    }
    const int stride = gridDim.x * blockDim.x;
    const int t0 = blockIdx.x * blockDim.x + threadIdx.x;
    for (int idx = t0; idx < total; idx += stride) out[idx] = bias[idx & 63];
    for (int idx = t0; idx < nx; idx += stride) g_xh[idx] = __float2half(x[idx]);
}

// Launch 1: column scan over per-block bins, then global bin prefix.
__global__ void scan_kernel(int nblocks) {
    __shared__ int tot[27];
    const int k = threadIdx.x;
    if (k < 27) {
        int s = 0;
        for (int b = 0; b < nblocks; ++b) { g_bbase[b * 27 + k] = s; s += g_bc[b * 27 + k]; }
        tot[k] = s;
    }
    __syncthreads();
    if (k == 0) {
        int s = 0;
        for (int b = 0; b < 27; ++b) { g_offsets[b] = s; s += tot[b]; }
        g_offsets[27] = s;
    }
    __syncthreads();
    if (k < 27) {
        int base = g_offsets[k];
        for (int b = 0; b < nblocks; ++b) g_bbase[b * 27 + k] += base;
    }
}

// Launch 2: scatter with deterministic bases + warp-aggregated rank.
__global__ void scatter_kernel(const int* __restrict__ ei,
                               const int* __restrict__ ej,
                               const int* __restrict__ ek, int E) {
    __shared__ int sbase[27], lc[27];
    if (threadIdx.x < 27) {
        sbase[threadIdx.x] = g_bbase[blockIdx.x * 27 + threadIdx.x];
        lc[threadIdx.x] = 0;
    }
    __syncthreads();
    const int lane = threadIdx.x & 31;
    const int b0 = blockIdx.x * SEG;
    const int b1 = min(E, b0 + SEG);
    for (int base = b0 + (threadIdx.x - lane); base < b1; base += blockDim.x) {
        const int e = base + lane;
        unsigned act = __ballot_sync(FULL, e < b1);
        if (e < b1) {
            int kk = ek[e];
            unsigned m = __match_any_sync(act, kk);
            int leader = __ffs(m) - 1;
            int rank   = __popc(m & ((1u << lane) - 1));
            int wb = 0;
            if (lane == leader) wb = atomicAdd(&lc[kk], __popc(m));
            wb = __shfl_sync(m, wb, leader);
            g_pij[sbase[kk] + wb + rank] = make_int2(ei[e], ej[e]);
        }
    }
}

#define PACK2(dst, lo, hi) \
    asm("mov.b64 %0, {%1, %2};" : "=l"(dst) : "f"(lo), "f"(hi))
// cvt half2 -> f32 pair, then fma.rn.f32x2 into acc (ptxas copy-props the pack)
#define CVTFMA(acc, h2, w)                                            \
    asm("{.reg .b16 l,h; .reg .f32 fl,fh; .reg .b64 xv;"              \
        " mov.b32 {l,h}, %1; cvt.f32.f16 fl, l; cvt.f32.f16 fh, h;"   \
        " mov.b64 xv, {fl,fh}; fma.rn.f32x2 %0, xv, %2, %0;}"         \
        : "+l"(acc) : "r"(h2), "l"(w))

// Launch 3: warp per edge, lane t owns out ch {2t,2t+1} of group g=t>>3.
// x row fp16 (128B = 1 line): 2 LDG.128/lane. Weights in regs per k-segment.
// Indices batched: 1 pij load per lane per 32 edges, distributed via shfl.
__global__ __launch_bounds__(256)
void compute_kernel(const float* __restrict__ weight,
                    float* __restrict__ out, int E, int nwarps) {
    const int wid = (blockIdx.x * blockDim.x + threadIdx.x) >> 5;
    const int t   = threadIdx.x & 31;
    const int g   = t >> 3;
    const int d0  = (2 * t) & 15;

    const int per = (E + nwarps - 1) / nwarps;
    int pos = wid * per;
    const int end = min(E, pos + per);
    const char* xb = (const char*)g_xh + g * 32;   // group slice base (bytes)

    while (pos < end) {
        int kk = 0;
        while (g_offsets[kk + 1] <= pos) ++kk;
        const int send = min(end, g_offsets[kk + 1]);

        // Weight pairs over input channels: wA -> out d0, wB -> out d0+1.
        unsigned long long wA[8], wB[8];
        const float* wb = weight + (g * 16) * 432 + d0 * 27 + kk;
#pragma unroll
        for (int p = 0; p < 8; ++p) {
            float a0 = __ldg(wb + (2 * p) * 432);
            float a1 = __ldg(wb + (2 * p + 1) * 432);
            PACK2(wA[p], a0, a1);
            float c0 = __ldg(wb + (2 * p) * 432 + 27);
            float c1 = __ldg(wb + (2 * p + 1) * 432 + 27);
            PACK2(wB[p], c0, c1);
        }

        int e0 = pos;
        while (e0 < send) {
            const int batch = min(32, send - e0);
            int2 ij = g_pij[e0 + min(t, batch - 1)];
            const int li = ij.x, lj = ij.y;

            int j0 = __shfl_sync(FULL, lj, 0);
            uint4 c0 = *(const uint4*)(xb + (size_t)j0 * 128);
            uint4 c1 = *(const uint4*)(xb + (size_t)j0 * 128 + 16);

            for (int b = 0; b < batch; ++b) {
                const int jn = __shfl_sync(FULL, lj, min(b + 1, batch - 1));
                uint4 n0 = *(const uint4*)(xb + (size_t)jn * 128);
                uint4 n1 = *(const uint4*)(xb + (size_t)jn * 128 + 16);
                const int ib = __shfl_sync(FULL, li, b);

                unsigned long long accA = 0ull, accB = 0ull;
                CVTFMA(accA, c0.x, wA[0]); CVTFMA(accB, c0.x, wB[0]);
                CVTFMA(accA, c0.y, wA[1]); CVTFMA(accB, c0.y, wB[1]);
                CVTFMA(accA, c0.z, wA[2]); CVTFMA(accB, c0.z, wB[2]);
                CVTFMA(accA, c0.w, wA[3]); CVTFMA(accB, c0.w, wB[3]);
                CVTFMA(accA, c1.x, wA[4]); CVTFMA(accB, c1.x, wB[4]);
                CVTFMA(accA, c1.y, wA[5]); CVTFMA(accB, c1.y, wB[5]);
                CVTFMA(accA, c1.z, wA[6]); CVTFMA(accB, c1.z, wB[6]);
                CVTFMA(accA, c1.w, wA[7]); CVTFMA(accB, c1.w, wB[7]);

                float a_lo, a_hi, b_lo, b_hi;
                asm("mov.b64 {%0, %1}, %2;" : "=f"(a_lo), "=f"(a_hi) : "l"(accA));
                asm("mov.b64 {%0, %1}, %2;" : "=f"(b_lo), "=f"(b_hi) : "l"(accB));
                const float r0 = a_lo + a_hi;
                const float r1 = b_lo + b_hi;

                float* dst = out + (size_t)ib * 64 + 2 * t;
                asm volatile("red.global.add.v2.f32 [%0], {%1, %2};"
                             :: "l"(dst), "f"(r0), "f"(r1) : "memory");

                c0 = n0; c1 = n1;
            }
            e0 += batch;
        }
        pos = send;
    }
}

extern "C" void kernel_launch(void* const* d_in, const int* in_sizes, int n_in,
                              void* d_out, int out_size) {
    const float* x  = (const float*)d_in[0];
    const int*   ei = (const int*)d_in[1];
    const int*   ej = (const int*)d_in[2];
    const int*   ek = (const int*)d_in[3];
    const float* w  = (const float*)d_in[5];
    const float* b  = (const float*)d_in[6];
    float*       out = (float*)d_out;

    const int E     = in_sizes[1];
    const int total = out_size;
    const int nx    = in_sizes[0];
    const int nhb   = (E + SEG - 1) / SEG;

    int dev = 0, sms = 148;
    cudaGetDevice(&dev);
    cudaDeviceGetAttribute(&sms, cudaDevAttrMultiProcessorCount, dev);

    const int prep_grid = max(nhb, 2 * sms);
    prep_kernel<<<prep_grid, 256>>>(ek, E, out, b, total, x, nx, nhb);
    scan_kernel<<<1, 32>>>(nhb);
    scatter_kernel<<<nhb, 256>>>(ei, ej, ek, E);

    const int grid   = 3 * sms;
    const int nwarps = grid * (256 / 32);
    compute_kernel<<<grid, 256>>>(w, out, E, nwarps);
}

// round 15
// speedup vs baseline: 1.6772x; 1.6772x over previous
#include <cuda_runtime.h>
#include <cstdint>

// GeneralConv: out[i] += W[k] @ x[j], E=2M, G=4 groups 16->16, + bias.
// R15: R8 structure (fp32 x, FFMA2 over input-channel pairs, plain smem-atomic
// counting sort) + 2-edge ILP in the compute loop (two independent acc chains,
// doubled MLP). Exactly 4 launches: prep, scan, scatter, compute.

static constexpr int CAP  = 2200000;
static constexpr int SEG  = 16384;
static constexpr int MAXB = (CAP + SEG - 1) / SEG + 1;

__device__ int2 g_pij[CAP];
__device__ int  g_bc[MAXB * 27];
__device__ int  g_bbase[MAXB * 27];
__device__ int  g_offsets[28];

// Launch 0: per-block k-histogram (plain smem atomics) + out = bias init.
__global__ void prep_kernel(const int* __restrict__ ek, int E,
                            float* __restrict__ out,
                            const float* __restrict__ bias, int total, int nhb) {
    if (blockIdx.x < nhb) {
        __shared__ int c[27];
        if (threadIdx.x < 27) c[threadIdx.x] = 0;
        __syncthreads();
        const int b0 = blockIdx.x * SEG;
        const int b1 = min(E, b0 + SEG);
        for (int e = b0 + threadIdx.x; e < b1; e += blockDim.x)
            atomicAdd(&c[ek[e]], 1);
        __syncthreads();
        if (threadIdx.x < 27) g_bc[blockIdx.x * 27 + threadIdx.x] = c[threadIdx.x];
    }
    const int stride = gridDim.x * blockDim.x;
    for (int idx = blockIdx.x * blockDim.x + threadIdx.x; idx < total; idx += stride)
        out[idx] = bias[idx & 63];
}

// Launch 1: column scan over per-block bins, then global bin prefix.
__global__ void scan_kernel(int nblocks) {
    __shared__ int tot[27];
    const int k = threadIdx.x;
    if (k < 27) {
        int s = 0;
        for (int b = 0; b < nblocks; ++b) { g_bbase[b * 27 + k] = s; s += g_bc[b * 27 + k]; }
        tot[k] = s;
    }
    __syncthreads();
    if (k == 0) {
        int s = 0;
        for (int b = 0; b < 27; ++b) { g_offsets[b] = s; s += tot[b]; }
        g_offsets[27] = s;
    }
    __syncthreads();
    if (k < 27) {
        int base = g_offsets[k];
        for (int b = 0; b < nblocks; ++b) g_bbase[b * 27 + k] += base;
    }
}

// Launch 2: single-pass scatter with deterministic per-block bases.
__global__ void scatter_kernel(const int* __restrict__ ei,
                               const int* __restrict__ ej,
                               const int* __restrict__ ek, int E) {
    __shared__ int base[27], lc[27];
    if (threadIdx.x < 27) {
        base[threadIdx.x] = g_bbase[blockIdx.x * 27 + threadIdx.x];
        lc[threadIdx.x] = 0;
    }
    __syncthreads();
    const int b0 = blockIdx.x * SEG;
    const int b1 = min(E, b0 + SEG);
    for (int e = b0 + threadIdx.x; e < b1; e += blockDim.x) {
        int kk = ek[e];
        int p  = base[kk] + atomicAdd(&lc[kk], 1);
        g_pij[p] = make_int2(ei[e], ej[e]);
    }
}

#define FMA2(acc, a, b) \
    asm("fma.rn.f32x2 %0, %1, %2, %0;" : "+l"(acc) : "l"(a), "l"(b))
#define PACK2(dst, lo, hi) \
    asm("mov.b64 %0, {%1, %2};" : "=l"(dst) : "f"(lo), "f"(hi))

// 8 FFMA2 into one acc chain from a 4x ulonglong2 row slice
#define EDGE_MATH(acc, cA, cB, cC, cD, W)                 \
    FMA2(acc, cA.x, W[0]); FMA2(acc, cA.y, W[1]);         \
    FMA2(acc, cB.x, W[2]); FMA2(acc, cB.y, W[3]);         \
    FMA2(acc, cC.x, W[4]); FMA2(acc, cC.y, W[5]);         \
    FMA2(acc, cD.x, W[6]); FMA2(acc, cD.y, W[7])

// Launch 3: warp per 2 edges/iter. Lane t owns out ch {2t,2t+1}, g=t>>3.
// fp32 x, input-channel-paired FFMA2 (no packing movs); 2 independent edges
// in flight per iteration for MLP/latency hiding.
__global__ __launch_bounds__(256)
void compute_kernel(const float* __restrict__ x,
                    const float* __restrict__ weight,
                    float* __restrict__ out, int E, int nwarps) {
    const int wid = (blockIdx.x * blockDim.x + threadIdx.x) >> 5;
    const int t   = threadIdx.x & 31;
    const int g   = t >> 3;
    const int d0  = (2 * t) & 15;

    const int per = (E + nwarps - 1) / nwarps;
    int pos = wid * per;
    const int end = min(E, pos + per);
    const float* xg = x + g * 16;

    while (pos < end) {
        int kk = 0;
        while (g_offsets[kk + 1] <= pos) ++kk;
        const int send = min(end, g_offsets[kk + 1]);

        // Weight pairs over input channels: wA -> out d0, wB -> out d0+1.
        unsigned long long wA[8], wB[8];
        const float* wb = weight + (g * 16) * 432 + d0 * 27 + kk;
#pragma unroll
        for (int p = 0; p < 8; ++p) {
            float a0 = __ldg(wb + (2 * p) * 432);
            float a1 = __ldg(wb + (2 * p + 1) * 432);
            PACK2(wA[p], a0, a1);
            float c0 = __ldg(wb + (2 * p) * 432 + 27);
            float c1 = __ldg(wb + (2 * p + 1) * 432 + 27);
            PACK2(wB[p], c0, c1);
        }

        int e = pos;
        // main loop: two edges per iteration, independent chains
        for (; e + 1 < send; e += 2) {
            const int2 ijp = g_pij[e];
            const int2 ijq = g_pij[e + 1];
            const ulonglong2* xp = (const ulonglong2*)(xg + (size_t)ijp.y * 64);
            const ulonglong2* xq = (const ulonglong2*)(xg + (size_t)ijq.y * 64);
            ulonglong2 p0 = xp[0], p1 = xp[1], p2 = xp[2], p3 = xp[3];
            ulonglong2 q0 = xq[0], q1 = xq[1], q2 = xq[2], q3 = xq[3];

            unsigned long long aA = 0ull, aB = 0ull, bA = 0ull, bB = 0ull;
            EDGE_MATH(aA, p0, p1, p2, p3, wA);
            EDGE_MATH(bA, q0, q1, q2, q3, wA);
            EDGE_MATH(aB, p0, p1, p2, p3, wB);
            EDGE_MATH(bB, q0, q1, q2, q3, wB);

            float al, ah, bl, bh, cl, ch, dl, dh;
            asm("mov.b64 {%0, %1}, %2;" : "=f"(al), "=f"(ah) : "l"(aA));
            asm("mov.b64 {%0, %1}, %2;" : "=f"(bl), "=f"(bh) : "l"(aB));
            asm("mov.b64 {%0, %1}, %2;" : "=f"(cl), "=f"(ch) : "l"(bA));
            asm("mov.b64 {%0, %1}, %2;" : "=f"(dl), "=f"(dh) : "l"(bB));

            float* dp = out + (size_t)ijp.x * 64 + 2 * t;
            float* dq = out + (size_t)ijq.x * 64 + 2 * t;
            asm volatile("red.global.add.v2.f32 [%0], {%1, %2};"
                         :: "l"(dp), "f"(al + ah), "f"(bl + bh) : "memory");
            asm volatile("red.global.add.v2.f32 [%0], {%1, %2};"
                         :: "l"(dq), "f"(cl + ch), "f"(dl + dh) : "memory");
        }
        // tail edge (at most one)
        if (e < send) {
            const int2 ijp = g_pij[e];
            const ulonglong2* xp = (const ulonglong2*)(xg + (size_t)ijp.y * 64);
            ulonglong2 p0 = xp[0], p1 = xp[1], p2 = xp[2], p3 = xp[3];
            unsigned long long aA = 0ull, aB = 0ull;
            EDGE_MATH(aA, p0, p1, p2, p3, wA);
            EDGE_MATH(aB, p0, p1, p2, p3, wB);
            float al, ah, bl, bh;
            asm("mov.b64 {%0, %1}, %2;" : "=f"(al), "=f"(ah) : "l"(aA));
            asm("mov.b64 {%0, %1}, %2;" : "=f"(bl), "=f"(bh) : "l"(aB));
            float* dp = out + (size_t)ijp.x * 64 + 2 * t;
            asm volatile("red.global.add.v2.f32 [%0], {%1, %2};"
                         :: "l"(dp), "f"(al + ah), "f"(bl + bh) : "memory");
            ++e;
        }
        pos = send;
    }
}

extern "C" void kernel_launch(void* const* d_in, const int* in_sizes, int n_in,
                              void* d_out, int out_size) {
    const float* x  = (const float*)d_in[0];
    const int*   ei = (const int*)d_in[1];
    const int*   ej = (const int*)d_in[2];
    const int*   ek = (const int*)d_in[3];
    const float* w  = (const float*)d_in[5];
    const float* b  = (const float*)d_in[6];
    float*       out = (float*)d_out;

    const int E     = in_sizes[1];
    const int total = out_size;
    const int nhb   = (E + SEG - 1) / SEG;

    int dev = 0, sms = 148;
    cudaGetDevice(&dev);
    cudaDeviceGetAttribute(&sms, cudaDevAttrMultiProcessorCount, dev);

    const int prep_grid = max(nhb, 2 * sms);
    prep_kernel<<<prep_grid, 256>>>(ek, E, out, b, total, nhb);
    scan_kernel<<<1, 32>>>(nhb);
    scatter_kernel<<<nhb, 256>>>(ei, ej, ek, E);

    const int grid   = 3 * sms;
    const int nwarps = grid * (256 / 32);
    compute_kernel<<<grid, 256>>>(x, w, out, E, nwarps);
}

// round 16
// speedup vs baseline: 1.9873x; 1.1849x over previous
#include <cuda_runtime.h>
#include <cuda_fp16.h>
#include <cstdint>

// GeneralConv: out[i] += W[k] @ x[j], E=2M, G=4 groups 16->16, + bias.
// R16: R8 pipeline/addressing (broadcast int2, per-lane addresses, 1-ahead
// prefetch, FFMA2 over input-channel pairs, red.v2) with x stored fp16
// (1 L1 line/row; 2 LDG.128/lane) converted to f32 ONCE per edge.
// Plain smem-atomic counting sort. Exactly 4 launches.

static constexpr int CAP  = 2200000;
static constexpr int SEG  = 16384;
static constexpr int MAXB = (CAP + SEG - 1) / SEG + 1;
static constexpr int NMAX = 100352;

__device__ int2 g_pij[CAP];
__device__ int  g_bc[MAXB * 27];
__device__ int  g_bbase[MAXB * 27];
__device__ int  g_offsets[28];
__device__ __align__(128) __half g_xh[NMAX * 64];

// Launch 0: per-block k-histogram + out=bias init + x->fp16 convert.
__global__ void prep_kernel(const int* __restrict__ ek, int E,
                            float* __restrict__ out,
                            const float* __restrict__ bias, int total,
                            const float* __restrict__ x, int nx, int nhb) {
    if (blockIdx.x < nhb) {
        __shared__ int c[27];
        if (threadIdx.x < 27) c[threadIdx.x] = 0;
        __syncthreads();
        const int b0 = blockIdx.x * SEG;
        const int b1 = min(E, b0 + SEG);
        for (int e = b0 + threadIdx.x; e < b1; e += blockDim.x)
            atomicAdd(&c[ek[e]], 1);
        __syncthreads();
        if (threadIdx.x < 27) g_bc[blockIdx.x * 27 + threadIdx.x] = c[threadIdx.x];
    }
    const int stride = gridDim.x * blockDim.x;
    const int t0 = blockIdx.x * blockDim.x + threadIdx.x;
    for (int idx = t0; idx < total; idx += stride) out[idx] = bias[idx & 63];
    for (int idx = t0; idx < nx; idx += stride) g_xh[idx] = __float2half(x[idx]);
}

// Launch 1: column scan over per-block bins, then global bin prefix.
__global__ void scan_kernel(int nblocks) {
    __shared__ int tot[27];
    const int k = threadIdx.x;
    if (k < 27) {
        int s = 0;
        for (int b = 0; b < nblocks; ++b) { g_bbase[b * 27 + k] = s; s += g_bc[b * 27 + k]; }
        tot[k] = s;
    }
    __syncthreads();
    if (k == 0) {
        int s = 0;
        for (int b = 0; b < 27; ++b) { g_offsets[b] = s; s += tot[b]; }
        g_offsets[27] = s;
    }
    __syncthreads();
    if (k < 27) {
        int base = g_offsets[k];
        for (int b = 0; b < nblocks; ++b) g_bbase[b * 27 + k] += base;
    }
}

// Launch 2: single-pass scatter with deterministic per-block bases.
__global__ void scatter_kernel(const int* __restrict__ ei,
                               const int* __restrict__ ej,
                               const int* __restrict__ ek, int E) {
    __shared__ int base[27], lc[27];
    if (threadIdx.x < 27) {
        base[threadIdx.x] = g_bbase[blockIdx.x * 27 + threadIdx.x];
        lc[threadIdx.x] = 0;
    }
    __syncthreads();
    const int b0 = blockIdx.x * SEG;
    const int b1 = min(E, b0 + SEG);
    for (int e = b0 + threadIdx.x; e < b1; e += blockDim.x) {
        int kk = ek[e];
        int p  = base[kk] + atomicAdd(&lc[kk], 1);
        g_pij[p] = make_int2(ei[e], ej[e]);
    }
}

#define FMA2(acc, a, b) \
    asm("fma.rn.f32x2 %0, %1, %2, %0;" : "+l"(acc) : "l"(a), "l"(b))
#define PACK2(dst, lo, hi) \
    asm("mov.b64 %0, {%1, %2};" : "=l"(dst) : "f"(lo), "f"(hi))
// one half2 word -> one f32x2 operand (2 cvt + pack; converted ONCE per edge)
#define H2TOF2(dst, u)                                     \
    do {                                                   \
        __half2 _h = *reinterpret_cast<const __half2*>(&(u)); \
        float2  _f = __half22float2(_h);                   \
        PACK2(dst, _f.x, _f.y);                            \
    } while (0)

// Launch 3: warp per edge (R8 pipeline). Lane t owns out ch {2t,2t+1}, g=t>>3.
// x row fp16: lane loads its 32B group slice as 2x LDG.128 (one line), converts
// 8 half2 -> 8 f32x2 once, then 16 FFMA2 (both output channels), 1 RED.v2.
__global__ __launch_bounds__(256)
void compute_kernel(const float* __restrict__ weight,
                    float* __restrict__ out, int E, int nwarps) {
    const int wid = (blockIdx.x * blockDim.x + threadIdx.x) >> 5;
    const int t   = threadIdx.x & 31;
    const int g   = t >> 3;
    const int d0  = (2 * t) & 15;

    const int per = (E + nwarps - 1) / nwarps;
    int pos = wid * per;
    const int end = min(E, pos + per);
    const char* xb = (const char*)g_xh + g * 32;   // group slice base (bytes)

    while (pos < end) {
        int kk = 0;
        while (g_offsets[kk + 1] <= pos) ++kk;
        const int send = min(end, g_offsets[kk + 1]);

        // Weight pairs over input channels: wA -> out d0, wB -> out d0+1.
        unsigned long long wA[8], wB[8];
        const float* wb = weight + (g * 16) * 432 + d0 * 27 + kk;
#pragma unroll
        for (int p = 0; p < 8; ++p) {
            float a0 = __ldg(wb + (2 * p) * 432);
            float a1 = __ldg(wb + (2 * p + 1) * 432);
            PACK2(wA[p], a0, a1);
            float c0 = __ldg(wb + (2 * p) * 432 + 27);
            float c1 = __ldg(wb + (2 * p + 1) * 432 + 27);
            PACK2(wB[p], c0, c1);
        }

        // 1-ahead software pipeline (R8 style): indices 2 ahead, x row 1 ahead.
        int2 ij0 = g_pij[pos];
        int2 ij1 = g_pij[min(pos + 1, send - 1)];
        uint4 cx0 = *(const uint4*)(xb + (size_t)ij0.y * 128);
        uint4 cx1 = *(const uint4*)(xb + (size_t)ij0.y * 128 + 16);

        for (int e = pos; e < send; ++e) {
            uint4 nx0 = *(const uint4*)(xb + (size_t)ij1.y * 128);
            uint4 nx1 = *(const uint4*)(xb + (size_t)ij1.y * 128 + 16);
            int2 ij2 = g_pij[min(e + 2, send - 1)];

            // convert once: 8 half2 -> 8 f32x2
            unsigned long long f[8];
            H2TOF2(f[0], cx0.x); H2TOF2(f[1], cx0.y);
            H2TOF2(f[2], cx0.z); H2TOF2(f[3], cx0.w);
            H2TOF2(f[4], cx1.x); H2TOF2(f[5], cx1.y);
            H2TOF2(f[6], cx1.z); H2TOF2(f[7], cx1.w);

            unsigned long long accA = 0ull, accB = 0ull;
#pragma unroll
            for (int p = 0; p < 8; ++p) {
                FMA2(accA, f[p], wA[p]);
                FMA2(accB, f[p], wB[p]);
            }

            float al, ah, bl, bh;
            asm("mov.b64 {%0, %1}, %2;" : "=f"(al), "=f"(ah) : "l"(accA));
            asm("mov.b64 {%0, %1}, %2;" : "=f"(bl), "=f"(bh) : "l"(accB));

            float* dst = out + (size_t)ij0.x * 64 + 2 * t;
            asm volatile("red.global.add.v2.f32 [%0], {%1, %2};"
                         :: "l"(dst), "f"(al + ah), "f"(bl + bh) : "memory");

            ij0 = ij1; ij1 = ij2;
            cx0 = nx0; cx1 = nx1;
        }
        pos = send;
    }
}

extern "C" void kernel_launch(void* const* d_in, const int* in_sizes, int n_in,
                              void* d_out, int out_size) {
    const float* x  = (const float*)d_in[0];
    const int*   ei = (const int*)d_in[1];
    const int*   ej = (const int*)d_in[2];
    const int*   ek = (const int*)d_in[3];
    const float* w  = (const float*)d_in[5];
    const float* b  = (const float*)d_in[6];
    float*       out = (float*)d_out;

    const int E     = in_sizes[1];
    const int total = out_size;
    const int nx    = in_sizes[0];
    const int nhb   = (E + SEG - 1) / SEG;

    int dev = 0, sms = 148;
    cudaGetDevice(&dev);
    cudaDeviceGetAttribute(&sms, cudaDevAttrMultiProcessorCount, dev);

    const int prep_grid = max(nhb, 2 * sms);
    prep_kernel<<<prep_grid, 256>>>(ek, E, out, b, total, x, nx, nhb);
    scan_kernel<<<1, 32>>>(nhb);
    scatter_kernel<<<nhb, 256>>>(ei, ej, ek, E);

    const int grid   = 3 * sms;
    const int nwarps = grid * (256 / 32);
    compute_kernel<<<grid, 256>>>(w, out, E, nwarps);
}